// round 17
// baseline (speedup 1.0000x reference)
#include <cuda_runtime.h>
#include <cuda_fp16.h>

#define B_ROWS 8192
#define HDIM   1024
#define NACC   2048

// ---------------- device scratch (no allocations allowed) ----------------
// g_Pf: A-fragment-ordered half2 P.  uint idx = ((row16*24 + slice16)*32 + lane)*4 + reg
__device__ __align__(1024) unsigned g_Pf[512 * 24 * 128];          // 6.3 MB
// g_Vf: B-fragment-ordered half2 V.  idx = (((g*16+n128)*12 + k16)*2 + wn)*512 + vg*128 + lane*4 + j
__device__ __align__(1024) unsigned g_Vf[2 * 16 * 12 * 1024];      // 1.57 MB
// g_Wf: B-fragment-ordered half2 U (stage-1 weights).
#define WFS 65536
__device__ __align__(1024) unsigned g_Wf[3 * WFS];                 // 786 KB
__device__ __align__(16)   float g_bias[4096];

#define VF_TOTAL (2 * 16 * 12 * 1024)
#define WF_TOTAL (3 * WFS)
#define PREP_TOTAL (VF_TOTAL + WF_TOTAL)

// ---------------- helpers ----------------
__device__ __forceinline__ unsigned pack_h2(float a, float b) {
    __half2 h = __floats2half2_rn(a, b);
    return *reinterpret_cast<unsigned*>(&h);
}
__device__ __forceinline__ float sigmoid_f(float x) {
    float e; asm("ex2.approx.f32 %0, %1;" : "=f"(e) : "f"(-x * 1.4426950408889634f));
    float r; asm("rcp.approx.f32 %0, %1;" : "=f"(r) : "f"(1.0f + e));
    return r;
}
__device__ __forceinline__ float tanh_f(float x) {
    return fmaf(2.0f, sigmoid_f(2.0f * x), -1.0f);
}
__device__ __forceinline__ void mma_f16(float* d, const unsigned* a, const unsigned* b) {
    asm volatile(
        "mma.sync.aligned.m16n8k16.row.col.f32.f16.f16.f32 "
        "{%0,%1,%2,%3}, {%4,%5,%6,%7}, {%8,%9}, {%0,%1,%2,%3};\n"
        : "+f"(d[0]), "+f"(d[1]), "+f"(d[2]), "+f"(d[3])
        : "r"(a[0]), "r"(a[1]), "r"(a[2]), "r"(a[3]), "r"(b[0]), "r"(b[1]));
}
__device__ __forceinline__ void cp_async16_sh(unsigned* smem_dst, const unsigned* gsrc) {
    unsigned d = (unsigned)__cvta_generic_to_shared(smem_dst);
    asm volatile("cp.async.cg.shared.global [%0], [%1], 16;" :: "r"(d), "l"(gsrc));
}
__device__ __forceinline__ void cp_async16_f(float* smem_dst, const float* gsrc) {
    unsigned d = (unsigned)__cvta_generic_to_shared(smem_dst);
    asm volatile("cp.async.cg.shared.global [%0], [%1], 16;" :: "r"(d), "l"(gsrc));
}

// ---------------- prep: g_Vf + g_Wf + combined bias (x/h conversion now fused into stage 1) ----------------
__global__ void prep_kernel(const float* __restrict__ v_x, const float* __restrict__ v_h0,
                            const float* __restrict__ v_h1, const float* __restrict__ u_x,
                            const float* __restrict__ u_h0, const float* __restrict__ u_h1,
                            const float* __restrict__ bx,  const float* __restrict__ bh) {
    int idx = blockIdx.x * 256 + threadIdx.x;
    if (idx < 4096) g_bias[idx] = bx[idx] + bh[idx];

    if (idx < VF_TOTAL) {
        int j    = idx & 3;
        int lane = (idx >> 2) & 31;
        int vg   = (idx >> 7) & 3;
        int rest = idx >> 9;
        int wn   = rest & 1;  rest >>= 1;
        int k16  = rest % 12; rest /= 12;
        int n128 = rest & 15;
        int g    = rest >> 4;

        int r    = vg * 4 + j;
        int nt   = r >> 1, kreg = r & 1;
        int g4   = lane >> 2, q = lane & 3;
        int k0   = k16 * 16 + 2 * q + kreg * 8;
        int gate = nt >> 1;
        int s    = n128 * 32 + wn * 16 + (nt & 1) * 8 + g4;

        float v[2];
#pragma unroll
        for (int e = 0; e < 2; e++) {
            int k = k0 + e;
            if (k < 64)       v[e] = v_x[(gate * 1024 + g * 512 + s) * 64 + k];
            else if (k < 128) v[e] = v_h0[(g * 64 + (k - 64)) * 2048 + gate * 512 + s];
            else              v[e] = v_h1[(g * 64 + (k - 128)) * 2048 + gate * 512 + s];
        }
        g_Vf[idx] = pack_h2(v[0], v[1]);
    } else if (idx < PREP_TOTAL) {
        int w    = idx - VF_TOTAL;
        int bt   = w / WFS;
        int rem  = w % WFS;
        int j    = rem & 3;
        int lane = (rem >> 2) & 31;
        int vg   = (rem >> 7) & 1;
        int wn   = (rem >> 8) & 3;
        int k16  = rem >> 10;

        int q = lane & 3, g4 = lane >> 2;
        int r = vg * 4 + j, nt = r >> 1, kreg = r & 1;
        int kb = k16 * 16 + 2 * q + kreg * 8;

        unsigned out = 0;
        bool ok = (bt == 0) ? (nt < 2) : (k16 < 32);
        if (ok) {
            int WN = (bt == 0) ? 16 : 32;
            int n  = wn * WN + nt * 8 + g4;
            float v[2];
#pragma unroll
            for (int e = 0; e < 2; e++) {
                int k = kb + e;
                if (bt == 0)      v[e] = u_x[k * 64 + n];
                else if (bt == 1) v[e] = (n < 64) ? u_h0[k * 64 + n]
                                                  : u_h1[(512 + k) * 64 + (n - 64)];
                else              v[e] = (n < 64) ? u_h1[k * 64 + n]
                                                  : u_h0[(512 + k) * 64 + (n - 64)];
            }
            out = pack_h2(v[0], v[1]);
        }
        g_Wf[w] = out;
    }
}

// ---------------- stage 1: fp32 A via cp.async smem staging, fp16 MMA -> g_Pf ----------------
// M=64 per CTA, 256 thr, 8 warps = 2 wm x 4 wn. A converted to half on fragment read.
#define S1_STRIDE 20
#define S1_STG    (64 * S1_STRIDE)        // floats per stage = 1280
#define S1_SMEM   (4 * S1_STG * 4)        // 20480 bytes

template<int NT, int NCH>
__device__ __forceinline__ void s1_body(const float* __restrict__ Asrc, int bt, int r0) {
    extern __shared__ float As[];
    int t = threadIdx.x, warp = t >> 5, lane = t & 31, g4 = lane >> 2, q = lane & 3;
    int wm = warp >> 2, wn = warp & 3;

    const unsigned* Wp = g_Wf + bt * WFS + wn * 256 + lane * 4;

    float acc[2][NT][4];
#pragma unroll
    for (int i = 0; i < 2; i++)
#pragma unroll
        for (int jn = 0; jn < NT; jn++)
#pragma unroll
            for (int l = 0; l < 4; l++) acc[i][jn][l] = 0.f;

    int crow = t >> 2, cq = t & 3;        // cp.async mapping: 64 rows x 4 x 16B
    auto issue = [&](int c) {
        if (c < NCH) {
            float* dst = As + (c & 3) * S1_STG;
            cp_async16_f(dst + crow * S1_STRIDE + cq * 4,
                         Asrc + (size_t)(r0 + crow) * 1024 + c * 16 + cq * 4);
        }
        asm volatile("cp.async.commit_group;" ::: "memory");
    };
    issue(0); issue(1); issue(2);

    uint4 b0[NT / 2], b1[NT / 2];
#pragma unroll
    for (int vg = 0; vg < NT / 2; vg++) b0[vg] = *(const uint4*)(Wp + vg * 128);

#pragma unroll 1
    for (int c = 0; c < NCH; c++) {
        asm volatile("cp.async.wait_group 2;" ::: "memory");
        __syncthreads();
        const float* Aa = As + (c & 3) * S1_STG;

        uint4* bc = (c & 1) ? b1 : b0;
        uint4* bn = (c & 1) ? b0 : b1;
        if (c + 1 < NCH) {
#pragma unroll
            for (int vg = 0; vg < NT / 2; vg++)
                bn[vg] = *(const uint4*)(Wp + (size_t)(c + 1) * 1024 + vg * 128);
        }

        unsigned af[2][4];
#pragma unroll
        for (int mt = 0; mt < 2; mt++) {
            int rb = wm * 32 + mt * 16;
            float2 v0 = *(const float2*)(Aa + (rb + g4) * S1_STRIDE + 2 * q);
            float2 v1 = *(const float2*)(Aa + (rb + g4 + 8) * S1_STRIDE + 2 * q);
            float2 v2 = *(const float2*)(Aa + (rb + g4) * S1_STRIDE + 2 * q + 8);
            float2 v3 = *(const float2*)(Aa + (rb + g4 + 8) * S1_STRIDE + 2 * q + 8);
            af[mt][0] = pack_h2(v0.x, v0.y);
            af[mt][1] = pack_h2(v1.x, v1.y);
            af[mt][2] = pack_h2(v2.x, v2.y);
            af[mt][3] = pack_h2(v3.x, v3.y);
        }

        const unsigned* bfp = (const unsigned*)bc;
#pragma unroll
        for (int mt = 0; mt < 2; mt++)
#pragma unroll
            for (int nt = 0; nt < NT; nt++)
                mma_f16(acc[mt][nt], af[mt], bfp + nt * 2);

        issue(c + 3);
    }

    // ---- store A-fragment-ordered half2 into g_Pf ----
    const int WN = NT * 8;
#pragma unroll
    for (int mt = 0; mt < 2; mt++) {
        int row16 = (r0 + wm * 32 + mt * 16) >> 4;
#pragma unroll
        for (int nt = 0; nt < NT; nt++) {
            int col = wn * WN + nt * 8;
            int slice;
            if (bt == 0)      slice = col >> 4;
            else if (bt == 1) slice = (col < 64) ? 4 + (col >> 4) : 20 + ((col - 64) >> 4);
            else              slice = (col < 64) ? 8 + (col >> 4) : 16 + ((col - 64) >> 4);
            unsigned p01 = pack_h2(acc[mt][nt][0], acc[mt][nt][1]);
            unsigned p23 = pack_h2(acc[mt][nt][2], acc[mt][nt][3]);
            size_t base = ((size_t)(row16 * 24 + slice) * 32 + lane) * 4 + ((col >> 3) & 1) * 2;
            g_Pf[base]     = p01;
            g_Pf[base + 1] = p23;
            if (bt == 0) {                       // rx duplicated into group-1 block
                g_Pf[base + 12 * 128]     = p01;
                g_Pf[base + 12 * 128 + 1] = p23;
            }
        }
    }
}

__global__ __launch_bounds__(256, 2) void stage1_kernel(const float* __restrict__ x,
                                                        const float* __restrict__ h) {
    int bt = blockIdx.y;
    int r0 = blockIdx.x * 64;
    if (bt == 0)      s1_body<2, 64>(x, 0, r0);
    else if (bt == 1) s1_body<4, 32>(h, 1, r0);
    else              s1_body<4, 32>(h + 512, 2, r0);
}

// ---------------- stage 2: B in SMEM (loaded once), A fragment-direct, fused epilogue ----------------
#define S2_SMEM 49152   // 12 chunks x 1024 uints x 4B = full B tile

__global__ __launch_bounds__(256, 2) void stage2_kernel(const float* __restrict__ cin,
                                                        float* __restrict__ out) {
    extern __shared__ unsigned Bs[];

    int r0 = blockIdx.x * 128, n128 = blockIdx.y, g = blockIdx.z;
    int s0 = n128 * 32;
    int t = threadIdx.x, warp = t >> 5, lane = t & 31, g4 = lane >> 2, q = lane & 3;
    int wm = warp & 3, wn = warp >> 2;          // 4 m-warps x 2 n-warps; warp tile 32x64

    const unsigned* Ap = g_Pf + ((size_t)((r0 >> 4) + wm * 2) * 24 + g * 12) * 128 + lane * 4;
    const unsigned* Bg = g_Vf + (size_t)(g * 16 + n128) * 12 * 1024;

    // ---- load the whole B tile into smem once (cp.async, single barrier) ----
#pragma unroll
    for (int i = 0; i < 12; i++)
        cp_async16_sh(Bs + (size_t)(i * 256 + t) * 4, Bg + (size_t)(i * 256 + t) * 4);
    asm volatile("cp.async.commit_group;" ::: "memory");

    float acc[2][8][4];
#pragma unroll
    for (int i = 0; i < 2; i++)
#pragma unroll
        for (int jn = 0; jn < 8; jn++)
#pragma unroll
            for (int l = 0; l < 4; l++) acc[i][jn][l] = 0.f;

    // A chunk-0 loads overlap the B smem fill
    uint4 a0[2], a1[2], b0[4], b1[4];
    a0[0] = *(const uint4*)(Ap);
    a0[1] = *(const uint4*)(Ap + 24 * 128);

    asm volatile("cp.async.wait_group 0;" ::: "memory");
    __syncthreads();

    const unsigned* Bp = Bs + wn * 512 + lane * 4;
#pragma unroll
    for (int vg = 0; vg < 4; vg++) b0[vg] = *(const uint4*)(Bp + vg * 128);

#pragma unroll
    for (int c = 0; c < 12; c++) {
        uint4* ac = (c & 1) ? a1 : a0;
        uint4* an = (c & 1) ? a0 : a1;
        uint4* bc = (c & 1) ? b1 : b0;
        uint4* bn = (c & 1) ? b0 : b1;
        if (c < 11) {                            // prefetch next chunk: A from L2, B from smem
            an[0] = *(const uint4*)(Ap + (size_t)(c + 1) * 128);
            an[1] = *(const uint4*)(Ap + (size_t)(c + 1) * 128 + 24 * 128);
#pragma unroll
            for (int vg = 0; vg < 4; vg++)
                bn[vg] = *(const uint4*)(Bp + (size_t)(c + 1) * 1024 + vg * 128);
        }
        const unsigned* af0 = (const unsigned*)&ac[0];
        const unsigned* af1 = (const unsigned*)&ac[1];
        const unsigned* bfp = (const unsigned*)bc;
#pragma unroll
        for (int nt = 0; nt < 8; nt++) {
            mma_f16(acc[0][nt], af0, bfp + nt * 2);
            mma_f16(acc[1][nt], af1, bfp + nt * 2);
        }
    }

    // ---- fused epilogue: gate = nt>>1, s = s0 + wn*16 + (nt&1)*8 + 2q + e ----
    float* out_h = out;
    float* out_c = out + (size_t)B_ROWS * HDIM;
#pragma unroll
    for (int mt = 0; mt < 2; mt++) {
#pragma unroll
        for (int rh = 0; rh < 2; rh++) {
            int row = r0 + wm * 32 + mt * 16 + g4 + rh * 8;
#pragma unroll
            for (int sh = 0; sh < 2; sh++) {
                int sbase = s0 + wn * 16 + sh * 8 + 2 * q;
                float hv2[2], cv2[2];
                float2 cvv = *(const float2*)&cin[(size_t)row * HDIM + g * 512 + sbase];
                float cvin[2] = { cvv.x, cvv.y };
#pragma unroll
                for (int e = 0; e < 2; e++) {
                    int s = sbase + e;
                    int l = rh * 2 + e;
                    float fp = acc[mt][0 + sh][l] + g_bias[0 * 1024 + g * 512 + s];
                    float ip = acc[mt][2 + sh][l] + g_bias[1 * 1024 + g * 512 + s];
                    float np = acc[mt][4 + sh][l] + g_bias[2 * 1024 + g * 512 + s];
                    float op = acc[mt][6 + sh][l] + g_bias[3 * 1024 + g * 512 + s];
                    float fg = sigmoid_f(fp), ig = sigmoid_f(ip), og = sigmoid_f(op);
                    float ng = tanh_f(np);
                    float cn = fg * cvin[e] + ig * ng;
                    hv2[e] = og * tanh_f(cn);
                    cv2[e] = cn;
                }
                size_t off = (size_t)row * HDIM + g * 512 + sbase;
                *(float2*)&out_h[off] = make_float2(hv2[0], hv2[1]);
                *(float2*)&out_c[off] = make_float2(cv2[0], cv2[1]);
            }
        }
    }
}

// ---------------- launch ----------------
extern "C" void kernel_launch(void* const* d_in, const int* in_sizes, int n_in,
                              void* d_out, int out_size) {
    const float* x    = (const float*)d_in[0];
    const float* h    = (const float*)d_in[1];
    const float* c    = (const float*)d_in[2];
    const float* u_x  = (const float*)d_in[3];
    const float* v_x  = (const float*)d_in[4];
    const float* u_h0 = (const float*)d_in[5];
    const float* v_h0 = (const float*)d_in[6];
    const float* u_h1 = (const float*)d_in[7];
    const float* v_h1 = (const float*)d_in[8];
    const float* bx   = (const float*)d_in[9];
    const float* bh   = (const float*)d_in[10];

    cudaFuncSetAttribute(stage2_kernel, cudaFuncAttributeMaxDynamicSharedMemorySize, S2_SMEM);

    int prep_blocks = (PREP_TOTAL + 255) / 256;
    prep_kernel<<<prep_blocks, 256>>>(v_x, v_h0, v_h1, u_x, u_h0, u_h1, bx, bh);
    stage1_kernel<<<dim3(128, 3), 256, S1_SMEM>>>(x, h);
    stage2_kernel<<<dim3(64, 16, 2), 256, S2_SMEM>>>(c, (float*)d_out);
}